// round 1
// baseline (speedup 1.0000x reference)
#include <cuda_runtime.h>
#include <math.h>

#define BB 64
#define TT 512
#define DO 128
#define DH 256
#define DL 16
#define KK 8
#define NTOK (BB*TT)
#define TILE 32
#define NBLK (NTOK/TILE)

#define Z_OFF ((size_t)NTOK*DO)
#define LOSS_OFF (Z_OFF + (size_t)NTOK*DL)

#define LOG2PI 1.8378770664093453f
// -0.5*log(2*pi*VAR), VAR=5e-4
#define C0R 2.8815126966116653f
#define INV2V 1000.0f

// ------------------ device scratch (no allocations allowed) ------------------
__device__ float g_E[NTOK*KK];     // exp(ev - m_t)
__device__ float g_m[NTOK];        // per-token max_k ev
__device__ float g_Linv0[KK*16*16];
__device__ float g_LinvT[KK*16*16];
__device__ float g_c0[KK];         // -0.5*(16*LOG2PI + logdet0)
__device__ float g_cT[KK];
__device__ float g_A[KK*KK];       // A[k][j] = exp(Qlog[k][j])
__device__ float g_piprob[KK];     // softmax(pi)
__device__ double g_acc[3];        // recon_sum, logq_sum, logZ_sum

// ------------------ init: zero accumulators ------------------
__global__ void init_kernel() {
    int t = threadIdx.x;
    if (t < 3) g_acc[t] = 0.0;
}

// ------------------ precompute: cholesky/Linv, A, pi ------------------
__global__ void pre_kernel(const float* __restrict__ init_cov,
                           const float* __restrict__ covs,
                           const float* __restrict__ Q,
                           const float* __restrict__ pi) {
    __shared__ float Ls[16][16][17];
    int tx = threadIdx.x;
    int w = tx >> 5, lane = tx & 31;
    if (w < 16) {
        int k = w & 7;
        const float* Cp = (w < 8 ? init_cov : covs) + k*256;
        // A = C C^T + 1e-6 I
        for (int e = lane; e < 256; e += 32) {
            int i = e >> 4, j = e & 15;
            float s = (i == j) ? 1e-6f : 0.0f;
            for (int m = 0; m < 16; m++) s += Cp[i*16+m]*Cp[j*16+m];
            Ls[w][i][j] = s;
        }
        __syncwarp();
        // in-place cholesky (lower), column by column
        for (int j = 0; j < 16; j++) {
            if (lane == 0) {
                float s = Ls[w][j][j];
                for (int m = 0; m < j; m++) s -= Ls[w][j][m]*Ls[w][j][m];
                Ls[w][j][j] = sqrtf(s);
            }
            __syncwarp();
            float djj = Ls[w][j][j];
            if (lane > j && lane < 16) {
                float s = Ls[w][lane][j];
                for (int m = 0; m < j; m++) s -= Ls[w][lane][m]*Ls[w][j][m];
                Ls[w][lane][j] = s / djj;
            }
            __syncwarp();
        }
        float logdet = 0.0f;
        for (int i = 0; i < 16; i++) logdet += logf(Ls[w][i][i]);
        logdet *= 2.0f;
        if (lane == 0) (w < 8 ? g_c0 : g_cT)[k] = -0.5f*(16.0f*LOG2PI + logdet);
        // Linv: column j solved by lane j
        if (lane < 16) {
            int j = lane;
            float X[16];
            for (int i = 0; i < 16; i++) X[i] = 0.0f;
            X[j] = 1.0f / Ls[w][j][j];
            for (int i = j+1; i < 16; i++) {
                float s = 0.0f;
                for (int m = j; m < i; m++) s -= Ls[w][i][m]*X[m];
                X[i] = s / Ls[w][i][i];
            }
            float* dst = (w < 8 ? g_Linv0 : g_LinvT) + k*256;
            for (int i = 0; i < 16; i++) dst[i*16+j] = X[i];
        }
    }
    // A = exp(log_softmax(Q, axis=-1).T) ; A[k][j] = softmax(Q[j])[k]
    if (tx < 8) {
        int j = tx;
        float mx = Q[j*8+0];
        for (int m = 1; m < 8; m++) mx = fmaxf(mx, Q[j*8+m]);
        float s = 0.0f;
        for (int m = 0; m < 8; m++) s += expf(Q[j*8+m]-mx);
        float lse = mx + logf(s);
        for (int k2 = 0; k2 < 8; k2++) g_A[k2*8+j] = expf(Q[j*8+k2]-lse);
    } else if (tx == 8) {
        float mx = pi[0];
        for (int m = 1; m < 8; m++) mx = fmaxf(mx, pi[m]);
        float s = 0.0f;
        for (int m = 0; m < 8; m++) s += expf(pi[m]-mx);
        for (int m = 0; m < 8; m++) g_piprob[m] = expf(pi[m]-mx)/s;
    }
}

// ------------------ encoder: x -> h -> enc -> z, logq ------------------
__global__ __launch_bounds__(256) void enc_kernel(
    const float* __restrict__ x, const float* __restrict__ eps,
    const float* __restrict__ W1, const float* __restrict__ b1,
    const float* __restrict__ W2, const float* __restrict__ b2,
    float* __restrict__ out)
{
    __shared__ float sbuf[32*257];   // W1 chunk (32x256) then h (32 x 256 pad 257)
    __shared__ float xs[32][33];
    __shared__ float encs[32][33];
    __shared__ float red[256];
    int tid = threadIdx.x;
    int tok0 = blockIdx.x * TILE;

    int jc = tid & 127;      // column pair base (jc, jc+128)
    int rh = tid >> 7;       // row half: rows rh*16 .. rh*16+15
    float acc0[16], acc1[16];
    {
        float b0 = b1[jc], bx = b1[jc+128];
        #pragma unroll
        for (int r = 0; r < 16; r++) { acc0[r] = b0; acc1[r] = bx; }
    }
    for (int c = 0; c < 4; c++) {
        int d0 = c * 32;
        __syncthreads();
        for (int e = tid; e < 1024; e += 256) {
            int r = e >> 5, d = e & 31;
            xs[r][d] = x[(size_t)(tok0+r)*DO + d0 + d];
        }
        #pragma unroll
        for (int d = 0; d < 32; d++) sbuf[d*256 + tid] = W1[(d0+d)*DH + tid];
        __syncthreads();
        #pragma unroll
        for (int d = 0; d < 32; d++) {
            float w0 = sbuf[d*256 + jc];
            float w1 = sbuf[d*256 + jc + 128];
            #pragma unroll
            for (int r = 0; r < 16; r++) {
                float xv = xs[rh*16 + r][d];
                acc0[r] += xv * w0;
                acc1[r] += xv * w1;
            }
        }
    }
    __syncthreads();
    // leaky -> h in smem
    #pragma unroll
    for (int r = 0; r < 16; r++) {
        int row = rh*16 + r;
        float h0 = acc0[r]; sbuf[row*257 + jc]       = (h0 > 0.f) ? h0 : 0.01f*h0;
        float h1 = acc1[r]; sbuf[row*257 + jc + 128] = (h1 > 0.f) ? h1 : 0.01f*h1;
    }
    __syncthreads();
    // enc = h @ W2 + b2 ; 32 tokens x 32 outputs
    {
        int o = tid & 31;
        int rg = tid >> 5;           // 0..7, rows rg*4..rg*4+3
        float e0 = b2[o], e1 = e0, e2 = e0, e3 = e0;
        for (int d = 0; d < 256; d++) {
            float w = W2[d*32 + o];
            e0 += sbuf[(rg*4+0)*257 + d] * w;
            e1 += sbuf[(rg*4+1)*257 + d] * w;
            e2 += sbuf[(rg*4+2)*257 + d] * w;
            e3 += sbuf[(rg*4+3)*257 + d] * w;
        }
        encs[rg*4+0][o] = e0; encs[rg*4+1][o] = e1;
        encs[rg*4+2][o] = e2; encs[rg*4+3][o] = e3;
    }
    __syncthreads();
    // z = mu + exp(0.5*lv)*eps ; logq partial = lv + eps^2
    float part = 0.0f;
    #pragma unroll
    for (int rep = 0; rep < 2; rep++) {
        int item = rep*256 + tid;
        int r = item >> 4, i = item & 15;
        float mu = encs[r][i], lv = encs[r][16+i];
        float e  = eps[(size_t)(tok0+r)*DL + i];
        float zv = mu + expf(0.5f*lv) * e;
        out[Z_OFF + (size_t)(tok0+r)*DL + i] = zv;
        part += lv + e*e;
    }
    red[tid] = part; __syncthreads();
    for (int st = 128; st > 0; st >>= 1) {
        if (tid < st) red[tid] += red[tid+st];
        __syncthreads();
    }
    if (tid == 0) {
        double contrib = -0.5 * ((double)red[0] + 32.0*16.0*(double)LOG2PI);
        atomicAdd(&g_acc[1], contrib);
    }
}

// ------------------ transitions + mvn logprob -> E, m ------------------
__global__ __launch_bounds__(256) void ev_kernel(
    const float* __restrict__ z,
    const float* __restrict__ Wt1, const float* __restrict__ bt1,
    const float* __restrict__ Wt2, const float* __restrict__ bt2,
    const float* __restrict__ init_mean)
{
    __shared__ float zall[33][17];   // tokens tok0-1 .. tok0+31
    __shared__ float hts[32*257];
    __shared__ float ds[32][17];
    __shared__ float ss[32][17];
    __shared__ float evs[32][9];
    int tid = threadIdx.x;
    int tok0 = blockIdx.x * TILE;
    int tloc0 = tok0 & (TT - 1);

    for (int e = tid; e < 33*16; e += 256) {
        int r = e >> 4, i = e & 15;
        float v = 0.0f;
        if (r > 0 || tloc0 > 0) v = z[(size_t)(tok0-1+r)*DL + i];
        zall[r][i] = v;
    }
    __syncthreads();

    for (int k = 0; k < KK; k++) {
        // ht = softplus(z_prev @ Wt1[k] + bt1[k]) ; thread = hidden col
        {
            float wv[16];
            #pragma unroll
            for (int d = 0; d < 16; d++) wv[d] = Wt1[(k*16+d)*256 + tid];
            float bb = bt1[k*256 + tid];
            #pragma unroll
            for (int r = 0; r < 32; r++) {
                float s = bb;
                #pragma unroll
                for (int d = 0; d < 16; d++) s += zall[r][d] * wv[d];
                float sp = fmaxf(s, 0.0f) + log1pf(__expf(-fabsf(s)));
                hts[r*257 + tid] = sp;
            }
        }
        __syncthreads();
        // means + diff
        {
            int i = tid & 15, r0 = tid >> 4;  // r0 in 0..15, rows r0 and r0+16
            float s0 = bt2[k*16 + i], s1 = s0;
            for (int d = 0; d < 256; d++) {
                float w = Wt2[(k*256+d)*16 + i];
                s0 += hts[r0*257 + d] * w;
                s1 += hts[(r0+16)*257 + d] * w;
            }
            bool init0 = (tloc0 == 0 && r0 == 0);
            float m0 = init0 ? init_mean[k*16 + i] : s0;
            ds[r0][i]    = zall[r0+1][i]  - m0;
            ds[r0+16][i] = zall[r0+17][i] - s1;
        }
        __syncthreads();
        // sol = Linv @ diff ; store sol^2
        {
            int i = tid & 15, r0 = tid >> 4;
            #pragma unroll
            for (int rep = 0; rep < 2; rep++) {
                int r = r0 + rep*16;
                bool isInit = (tloc0 == 0 && r == 0);
                const float* Li = (isInit ? g_Linv0 : g_LinvT) + k*256 + i*16;
                float s = 0.0f;
                #pragma unroll
                for (int j = 0; j < 16; j++) s += Li[j] * ds[r][j];
                ss[r][i] = s * s;
            }
        }
        __syncthreads();
        if (tid < 32) {
            int r = tid;
            bool isInit = (tloc0 == 0 && r == 0);
            float c = (isInit ? g_c0 : g_cT)[k];
            float s = 0.0f;
            #pragma unroll
            for (int i = 0; i < 16; i++) s += ss[r][i];
            evs[r][k] = c - 0.5f * s;
        }
        __syncthreads();
    }
    // E = exp(ev - m), m = max_k ev
    {
        int r = tid >> 3, k = tid & 7;
        float m = evs[r][0];
        #pragma unroll
        for (int j = 1; j < 8; j++) m = fmaxf(m, evs[r][j]);
        g_E[(size_t)(tok0+r)*KK + k] = __expf(evs[r][k] - m);
        if (k == 0) g_m[tok0+r] = m;
    }
}

// ------------------ HMM forward scan (rescaled linear space) ------------------
__global__ void hmm_kernel() {
    int b = blockIdx.x;
    int lane = threadIdx.x & 31;
    int k = lane & 7;
    float a[8];
    #pragma unroll
    for (int j = 0; j < 8; j++) a[j] = g_A[k*8 + j];
    const float* Eb = g_E + (size_t)b*TT*KK;
    const float* mb = g_m + (size_t)b*TT;
    // t = 0
    float u = Eb[k] * g_piprob[k];
    float c = u;
    #pragma unroll
    for (int st = 1; st < 8; st <<= 1) c += __shfl_xor_sync(0xffffffffu, c, st, 8);
    float alpha = u / c;
    float acc = mb[0];
    float prod = c;
    float eN = Eb[8 + k], mN = mb[1];
    for (int t = 1; t < TT; t++) {
        float e = eN, m = mN;
        int tn = (t+1 < TT) ? (t+1) : t;
        eN = Eb[tn*8 + k]; mN = mb[tn];
        float s = 0.0f;
        #pragma unroll
        for (int j = 0; j < 8; j++)
            s += a[j] * __shfl_sync(0xffffffffu, alpha, j, 8);
        u = e * s;
        c = u;
        #pragma unroll
        for (int st = 1; st < 8; st <<= 1) c += __shfl_xor_sync(0xffffffffu, c, st, 8);
        alpha = u / c;
        acc += m;
        prod *= c;
        if ((t & 7) == 7) { acc += __logf(prod); prod = 1.0f; }
    }
    acc += __logf(prod);
    if (threadIdx.x == 0) atomicAdd(&g_acc[2], (double)acc);
}

// ------------------ decoder + recon ------------------
__global__ __launch_bounds__(256) void dec_kernel(
    const float* __restrict__ z,
    const float* __restrict__ Wd1, const float* __restrict__ bd1,
    const float* __restrict__ Wd2, const float* __restrict__ bd2,
    const float* __restrict__ x, float* __restrict__ out)
{
    __shared__ float zs[32][17];
    __shared__ float hds[32*257];
    __shared__ float red[256];
    int tid = threadIdx.x;
    int tok0 = blockIdx.x * TILE;

    for (int e = tid; e < 512; e += 256) {
        int r = e >> 4, i = e & 15;
        zs[r][i] = z[(size_t)(tok0+r)*DL + i];
    }
    __syncthreads();
    // hd = leaky(z @ Wd1 + bd1)
    {
        float wv[16];
        #pragma unroll
        for (int d = 0; d < 16; d++) wv[d] = Wd1[d*256 + tid];
        float bb = bd1[tid];
        #pragma unroll
        for (int r = 0; r < 32; r++) {
            float s = bb;
            #pragma unroll
            for (int d = 0; d < 16; d++) s += zs[r][d] * wv[d];
            hds[r*257 + tid] = (s > 0.f) ? s : 0.01f*s;
        }
    }
    __syncthreads();
    // x_hat = hd @ Wd2 + bd2 ; recon partials
    float part = 0.0f;
    {
        int j = tid & 127, rh = tid >> 7;  // rows rh*16..rh*16+15
        float accs[16];
        float bb = bd2[j];
        #pragma unroll
        for (int r = 0; r < 16; r++) accs[r] = bb;
        for (int d = 0; d < 256; d++) {
            float w = Wd2[d*128 + j];
            #pragma unroll
            for (int r = 0; r < 16; r++)
                accs[r] += hds[(rh*16+r)*257 + d] * w;
        }
        #pragma unroll
        for (int r = 0; r < 16; r++) {
            int tk = tok0 + rh*16 + r;
            float xh = accs[r];
            out[(size_t)tk*DO + j] = xh;
            float dv = x[(size_t)tk*DO + j] - xh;
            part += C0R - dv*dv*INV2V;
        }
    }
    red[tid] = part; __syncthreads();
    for (int st = 128; st > 0; st >>= 1) {
        if (tid < st) red[tid] += red[tid+st];
        __syncthreads();
    }
    if (tid == 0) atomicAdd(&g_acc[0], (double)red[0]);
}

// ------------------ finalize loss ------------------
__global__ void fin_kernel(float* __restrict__ out) {
    double recon = g_acc[0] / (double)BB;
    double ent   = -g_acc[1] / (double)BB;
    double msm   = g_acc[2] / (double)BB;
    out[LOSS_OFF] = (float)(-(recon + ent + msm));
}

extern "C" void kernel_launch(void* const* d_in, const int* in_sizes, int n_in,
                              void* d_out, int out_size) {
    const float* x        = (const float*)d_in[0];
    const float* eps      = (const float*)d_in[1];
    const float* W1       = (const float*)d_in[2];
    const float* b1       = (const float*)d_in[3];
    const float* W2       = (const float*)d_in[4];
    const float* b2       = (const float*)d_in[5];
    const float* Wt1      = (const float*)d_in[6];
    const float* bt1      = (const float*)d_in[7];
    const float* Wt2      = (const float*)d_in[8];
    const float* bt2      = (const float*)d_in[9];
    const float* Wd1      = (const float*)d_in[10];
    const float* bd1      = (const float*)d_in[11];
    const float* Wd2      = (const float*)d_in[12];
    const float* bd2      = (const float*)d_in[13];
    const float* Q        = (const float*)d_in[14];
    const float* pi       = (const float*)d_in[15];
    const float* init_mean= (const float*)d_in[16];
    const float* init_cov = (const float*)d_in[17];
    const float* covs     = (const float*)d_in[18];
    float* out = (float*)d_out;

    init_kernel<<<1, 32>>>();
    pre_kernel<<<1, 512>>>(init_cov, covs, Q, pi);
    enc_kernel<<<NBLK, 256>>>(x, eps, W1, b1, W2, b2, out);
    ev_kernel<<<NBLK, 256>>>(out + Z_OFF, Wt1, bt1, Wt2, bt2, init_mean);
    dec_kernel<<<NBLK, 256>>>(out + Z_OFF, Wd1, bd1, Wd2, bd2, x, out);
    hmm_kernel<<<BB, 32>>>();
    fin_kernel<<<1, 1>>>(out);
}